// round 10
// baseline (speedup 1.0000x reference)
#include <cuda_runtime.h>
#include <cuda_bf16.h>
#include <stdint.h>

#define BB 64
#define RR 32
#define NN 16384
#define DD 64
#define OO 8
#define CPB 4                 // chunks (CTAs) per batch
#define CHUNK (NN / CPB)      // 4096
#define THREADS 256
#define NW (THREADS / 32)     // 8 warps
#define CAP 512

// Per-CTA private slots (plain stores, overwritten every run -> no reset needed)
__device__ float g_part[BB * CPB * DD];
__device__ int   g_pcnt[BB * CPB];
// Arrive tickets (reset by last block each run)
__device__ int   g_arrive[BB];

__global__ __launch_bounds__(THREADS) void fused_kernel(
    const float* __restrict__ h_context,   // [B,N,D]
    const float* __restrict__ l_local,     // [B,R,D]
    const float* __restrict__ lambda_so,   // [R,O]
    const int*   __restrict__ center_o,    // [B]
    const int*   __restrict__ o_types,     // [B,N]
    const int*   __restrict__ adj,         // [B,N] bool as int32
    const int*   __restrict__ two,         // [B,N] bool as int32
    float*       __restrict__ out)         // [B,R]
{
    const int b    = blockIdx.x >> 2;          // / CPB
    const int c    = blockIdx.x & (CPB - 1);
    const int tid  = threadIdx.x;
    const int wid  = tid >> 5;
    const int lane = tid & 31;

    __shared__ int   s_idx[CAP];
    __shared__ float s_part[NW * DD];
    __shared__ float s_vec[DD];
    __shared__ float s_ll[RR * DD];            // prefetched l_local rows (8KB)
    __shared__ float s_lam[RR];
    __shared__ int   s_cnt;
    __shared__ int   s_last;
    __shared__ int   s_nv;

    if (tid == 0) s_cnt = 0;

    const int co = __ldg(&center_o[b]);

    // ---- Early prefetch: l_local rows for this batch + lambda column ----
    {
        const float4* ll4 = reinterpret_cast<const float4*>(l_local + (size_t)b * RR * DD);
        float4* sl4 = reinterpret_cast<float4*>(s_ll);
        sl4[tid]       = ll4[tid];
        sl4[tid + 256] = ll4[tid + 256];
        if (tid < RR) s_lam[tid] = lambda_so[tid * OO + co];
    }

    // ---- Phase A: mask scan, MLP=12 ----
    const int4* ot4 = reinterpret_cast<const int4*>(o_types + b * NN + c * CHUNK);
    const int4* ad4 = reinterpret_cast<const int4*>(adj     + b * NN + c * CHUNK);
    const int4* tw4 = reinterpret_cast<const int4*>(two     + b * NN + c * CHUNK);

    int4 tt[4], aa[4], ww[4];
    #pragma unroll
    for (int j = 0; j < 4; j++) {
        tt[j] = ot4[tid + j * 256];
        aa[j] = ad4[tid + j * 256];
        ww[j] = tw4[tid + j * 256];
    }
    __syncthreads();   // covers s_cnt init (prefetch stores unordered w.r.t. this, fine)

    // ---- Ballot-aggregated compaction: 1 smem atomic per warp per group ----
    #pragma unroll
    for (int j = 0; j < 4; j++) {
        const int n0 = c * CHUNK + (j * 256 + tid) * 4;
        const bool w0 = (aa[j].x | ww[j].x) && tt[j].x == co;
        const bool w1 = (aa[j].y | ww[j].y) && tt[j].y == co;
        const bool w2 = (aa[j].z | ww[j].z) && tt[j].z == co;
        const bool w3 = (aa[j].w | ww[j].w) && tt[j].w == co;
        const unsigned b0 = __ballot_sync(0xffffffffu, w0);
        const unsigned b1 = __ballot_sync(0xffffffffu, w1);
        const unsigned b2 = __ballot_sync(0xffffffffu, w2);
        const unsigned b3 = __ballot_sync(0xffffffffu, w3);
        const int tot = __popc(b0) + __popc(b1) + __popc(b2) + __popc(b3);
        int wbase = 0;
        if (lane == 0 && tot) wbase = atomicAdd(&s_cnt, tot);
        wbase = __shfl_sync(0xffffffffu, wbase, 0);
        const unsigned lt = (1u << lane) - 1u;
        int p0 = wbase + __popc(b0 & lt);
        int p1 = wbase + __popc(b0) + __popc(b1 & lt);
        int p2 = wbase + __popc(b0) + __popc(b1) + __popc(b2 & lt);
        int p3 = wbase + __popc(b0) + __popc(b1) + __popc(b2) + __popc(b3 & lt);
        if (w0 && p0 < CAP) s_idx[p0] = n0 + 0;
        if (w1 && p1 < CAP) s_idx[p1] = n0 + 1;
        if (w2 && p2 < CAP) s_idx[p2] = n0 + 2;
        if (w3 && p3 < CAP) s_idx[p3] = n0 + 3;
    }
    __syncthreads();
    int cnt = s_cnt;
    if (cnt > CAP) cnt = CAP;

    // ---- Phase B: gather + per-row normalize; half-warp per row ----
    const int half = lane >> 4;
    const int l16  = lane & 15;
    float a0 = 0.0f, a1 = 0.0f, a2 = 0.0f, a3 = 0.0f;

    for (int k0 = wid * 2; k0 < cnt; k0 += NW * 2) {
        const int k = k0 + half;
        float4 v = make_float4(0.0f, 0.0f, 0.0f, 0.0f);
        if (k < cnt) {
            const int n = s_idx[k];
            v = reinterpret_cast<const float4*>(
                    h_context + ((size_t)b * NN + n) * DD)[l16];
        }
        float sq = v.x * v.x + v.y * v.y + v.z * v.z + v.w * v.w;
        sq += __shfl_xor_sync(0xffffffffu, sq, 8);
        sq += __shfl_xor_sync(0xffffffffu, sq, 4);
        sq += __shfl_xor_sync(0xffffffffu, sq, 2);
        sq += __shfl_xor_sync(0xffffffffu, sq, 1);
        const float sc = rsqrtf(fmaxf(sq, 1e-12f));
        a0 += sc * v.x; a1 += sc * v.y; a2 += sc * v.z; a3 += sc * v.w;
    }
    a0 += __shfl_xor_sync(0xffffffffu, a0, 16);
    a1 += __shfl_xor_sync(0xffffffffu, a1, 16);
    a2 += __shfl_xor_sync(0xffffffffu, a2, 16);
    a3 += __shfl_xor_sync(0xffffffffu, a3, 16);
    if (lane < 16)
        reinterpret_cast<float4*>(s_part + wid * DD)[l16] =
            make_float4(a0, a1, a2, a3);
    __syncthreads();

    // ---- Reduce 8 warps, publish this CTA's slot (plain STG) ----
    const int slot = b * CPB + c;
    if (tid < DD) {
        float s = 0.0f;
        #pragma unroll
        for (int w2i = 0; w2i < NW; w2i++) s += s_part[w2i * DD + tid];
        g_part[slot * DD + tid] = s;
    }
    if (tid == 0) g_pcnt[slot] = cnt;
    __threadfence();
    __syncthreads();

    if (tid == 0)
        s_last = (atomicAdd(&g_arrive[b], 1) == CPB - 1);
    __syncthreads();
    if (!s_last) return;

    // ---- Last block of batch b: combine 4 slots + epilogue ----
    __threadfence();   // acquire side
    if (tid < DD) {
        float s = 0.0f;
        #pragma unroll
        for (int k = 0; k < CPB; k++)
            s += __ldcg(&g_part[(b * CPB + k) * DD + tid]);
        s_vec[tid] = s;
    }
    if (tid == 0) {
        int nv = 0;
        #pragma unroll
        for (int k = 0; k < CPB; k++) nv += __ldcg(&g_pcnt[b * CPB + k]);
        s_nv = nv;
        g_arrive[b] = 0;   // reset for next graph replay
    }
    __syncthreads();

    const float nv = (float)s_nv;
    const float inv_nv_avg = 1.0f / fmaxf(nv, 1e-9f);
    const float scale_lam  = 1.0f / fmaxf(nv, 1.0f);

    // 8 warps x 4 rows = 32 rows; all data in smem
    #pragma unroll
    for (int rr = 0; rr < RR / NW; rr++) {
        const int r = wid + rr * NW;
        const float2 v  = reinterpret_cast<const float2*>(s_ll + r * DD)[lane];
        const float2 sv = reinterpret_cast<const float2*>(s_vec)[lane];
        float sq = v.x * v.x + v.y * v.y;
        float dp = v.x * sv.x + v.y * sv.y;
        #pragma unroll
        for (int o = 16; o; o >>= 1) {
            sq += __shfl_xor_sync(0xffffffffu, sq, o);
            dp += __shfl_xor_sync(0xffffffffu, dp, o);
        }
        if (lane == 0) {
            const float inv = rsqrtf(fmaxf(sq, 1e-12f));
            const float avg = dp * inv * inv_nv_avg;
            out[b * RR + r] = fmaxf(s_lam[r] * scale_lam, 0.0f) * (1.0f - avg);
        }
    }
}

extern "C" void kernel_launch(void* const* d_in, const int* in_sizes, int n_in,
                              void* d_out, int out_size) {
    const float* l_local   = (const float*)d_in[0];
    const float* h_context = (const float*)d_in[1];
    const float* lambda_so = (const float*)d_in[2];
    const int*   center_o  = (const int*)d_in[3];
    const int*   o_types   = (const int*)d_in[4];
    const int*   adj_mask  = (const int*)d_in[5];
    const int*   two_hop   = (const int*)d_in[6];
    float* out = (float*)d_out;

    fused_kernel<<<BB * CPB, THREADS>>>(h_context, l_local, lambda_so,
                                        center_o, o_types, adj_mask, two_hop, out);
}